// round 8
// baseline (speedup 1.0000x reference)
#include <cuda_runtime.h>
#include <cstdint>

#define D_DIM 768
#define OUT_DIM 196
#define NPAD 208
#define TM 128
#define BK 32
#define NTILES 24
#define XSTAGES 5
#define WSTAGES 4
#define NFRAG 13

#define XROWW 36                      // x row stride (words): 4g+t conflict-free
#define XW (TM * XROWW)               // 4608 words / stage
#define WROWW 40                      // W row stride (words) = 20 float2: 64-bit CF
#define WW (NPAD * WROWW)             // 8320 words / stage

#define X_OFF 0
#define W_OFF (XSTAGES * XW)                       // 23040
#define MEAN_OFF (W_OFF + WSTAGES * WW)            // 56320
#define RSTD_OFF (MEAN_OFF + TM)
#define SP_OFF (RSTD_OFF + TM)
#define CB_OFF (SP_OFF + NPAD)
#define SMEM_WORDS (CB_OFF + NPAD)                 // 56992
#define SMEM_BYTES (SMEM_WORDS * 4)                // 227968 (< 232448 limit)

__device__ float g_wp[NTILES * NPAD * WROWW];  // pair-interleaved, tf32-rounded gamma*W
__device__ float g_sp[NPAD];                   // row sums of gamma*W (tf32-rounded terms)
__device__ float g_cb[NPAD];                   // beta.W + bias

__device__ __forceinline__ uint32_t f2tf32(float f) {
    uint32_t u;
    asm("cvt.rna.tf32.f32 %0, %1;" : "=r"(u) : "f"(f));
    return u;
}
__device__ __forceinline__ void mma_tf32(float* c, const uint32_t* a, const uint32_t* b) {
    asm volatile(
        "mma.sync.aligned.m16n8k8.row.col.f32.tf32.tf32.f32 "
        "{%0,%1,%2,%3}, {%4,%5,%6,%7}, {%8,%9}, {%0,%1,%2,%3};"
        : "+f"(c[0]), "+f"(c[1]), "+f"(c[2]), "+f"(c[3])
        : "r"(a[0]), "r"(a[1]), "r"(a[2]), "r"(a[3]), "r"(b[0]), "r"(b[1]));
}
__device__ __forceinline__ void cp16(float* dst, const float* src) {
    uint32_t d = (uint32_t)__cvta_generic_to_shared(dst);
    asm volatile("cp.async.cg.shared.global [%0], [%1], 16;" :: "r"(d), "l"(src));
}

// ---------------- Prologue: fold gamma into W, pair-interleave, precompute sums ----------------
__global__ void prep_kernel(const float* __restrict__ W,
                            const float* __restrict__ gamma,
                            const float* __restrict__ beta,
                            const float* __restrict__ bias)
{
    __shared__ float rs_[24], rc_[24];
    const int n = blockIdx.x;           // 0..207
    const int k = threadIdx.x;          // 0..767
    const int lane = k & 31, wid = k >> 5;

    float wp = 0.f, cb = 0.f;
    if (n < OUT_DIM) {
        float w = W[n * D_DIM + k];
        wp = __uint_as_float(f2tf32(w * gamma[k]));
        cb = beta[k] * w;
    }
    // pair-interleaved store: tile kt, pair p = ks*4+t holds (k, k+4)
    {
        int kt = k >> 5, kk = k & 31;
        int ks = kk >> 3, r8 = kk & 7;
        int p  = ks * 4 + (r8 & 3);
        int hi = r8 >> 2;
        g_wp[(kt * NPAD + n) * WROWW + p * 2 + hi] = wp;
    }
    // zero the 8 pad words (32..39) of each of the 24 tile-rows
    if (k < 192) {
        int kt = k >> 3;
        g_wp[(kt * NPAD + n) * WROWW + 32 + (k & 7)] = 0.f;
    }

    float s1 = wp;
    #pragma unroll
    for (int off = 16; off; off >>= 1) {
        s1 += __shfl_xor_sync(0xffffffffu, s1, off);
        cb += __shfl_xor_sync(0xffffffffu, cb, off);
    }
    if (lane == 0) { rs_[wid] = s1; rc_[wid] = cb; }
    __syncthreads();
    if (k < 32) {
        float a = (k < 24) ? rs_[k] : 0.f;
        float c = (k < 24) ? rc_[k] : 0.f;
        #pragma unroll
        for (int off = 16; off; off >>= 1) {
            a += __shfl_xor_sync(0xffffffffu, a, off);
            c += __shfl_xor_sync(0xffffffffu, c, off);
        }
        if (k == 0) {
            g_sp[n] = a;
            g_cb[n] = (n < OUT_DIM) ? (c + bias[n]) : 0.f;
        }
    }
}

// ---------------- Main: split 5/4-stage pipeline, 1 barrier per tile ----------------
__global__ __launch_bounds__(256, 1)
void ln_gemm_kernel(const float* __restrict__ x, float* __restrict__ out)
{
    extern __shared__ float smem[];
    const int tid  = threadIdx.x;
    const int lane = tid & 31;
    const int wrp  = tid >> 5;
    const long long R0 = (long long)blockIdx.x * TM;

    const int warp_m = wrp & 3;
    const int warp_n = wrp >> 2;
    const int grp = lane >> 2;
    const int tig = lane & 3;
    const int nf0 = warp_n * NFRAG;

    if (tid < NPAD) {
        smem[SP_OFF + tid] = g_sp[tid];
        smem[CB_OFF + tid] = g_cb[tid];
    }

    const float* xg = x + R0 * D_DIM;

    // ---- fill helpers (inlined via lambdas) ----
    auto fill_x = [&](int tile, int stage) {
        float* xd = smem + X_OFF + stage * XW;
        const float* src = xg + tile * BK;
        #pragma unroll
        for (int i = 0; i < 4; i++) {
            int idx = tid + i * 256;          // 1024 16B chunks
            int r = idx >> 3, c = idx & 7;
            cp16(xd + r * XROWW + c * 4, src + r * D_DIM + c * 4);
        }
    };
    auto fill_w = [&](int tile, int stage) {
        float* wd = smem + W_OFF + stage * WW;
        const float* src = g_wp + tile * NPAD * WROWW;
        #pragma unroll
        for (int i = 0; i < 9; i++) {
            int idx = tid + i * 256;          // 2080 16B chunks
            if (idx < NPAD * 10) {
                int r = idx / 10, c = idx % 10;
                cp16(wd + r * WROWW + c * 4, src + r * WROWW + c * 4);
            }
        }
    };

    // Prologue groups: g0={x0,x1,W0}, g1={x2,W1}, g2={x3,W2}
    fill_x(0, 0); fill_x(1, 1); fill_w(0, 0);
    asm volatile("cp.async.commit_group;");
    fill_x(2, 2); fill_w(1, 1);
    asm volatile("cp.async.commit_group;");
    fill_x(3, 3); fill_w(2, 2);
    asm volatile("cp.async.commit_group;");

    float acc[2][NFRAG][4];
    #pragma unroll
    for (int s = 0; s < 2; s++)
        #pragma unroll
        for (int j = 0; j < NFRAG; j++)
            #pragma unroll
            for (int q = 0; q < 4; q++) acc[s][j][q] = 0.f;

    float ss = 0.f, ss2 = 0.f;
    const int srow = tid >> 1;
    const int soff = (tid & 1) * 16;

    // stats + tf32 roundback of one x stage
    auto stats_round = [&](int stage) {
        float* xb = smem + X_OFF + stage * XW + srow * XROWW + soff;
        #pragma unroll
        for (int i = 0; i < 4; i++) {
            float4* p = reinterpret_cast<float4*>(xb + i * 4);
            float4 v = *p;
            ss  += (v.x + v.y) + (v.z + v.w);
            ss2 += v.x * v.x + v.y * v.y + v.z * v.z + v.w * v.w;
            v.x = __uint_as_float(f2tf32(v.x));
            v.y = __uint_as_float(f2tf32(v.y));
            v.z = __uint_as_float(f2tf32(v.z));
            v.w = __uint_as_float(f2tf32(v.w));
            *p = v;
        }
    };

    // Pre-loop: round tile 0
    asm volatile("cp.async.wait_group 2;");
    __syncthreads();
    stats_round(0);

    int st5 = 0, st4 = 0;                // kt % 5, kt % 4
    for (int kt = 0; kt < NTILES; kt++) {
        asm volatile("cp.async.wait_group 2;");
        __syncthreads();

        // refill early: x tile kt+4 -> stage (kt+4)%5, W tile kt+3 -> (kt+3)%4
        {
            int sx = st5 + 4; if (sx >= 5) sx -= 5;
            int sw = st4 + 3; if (sw >= 4) sw -= 4;
            if (kt + 4 < NTILES) fill_x(kt + 4, sx);
            if (kt + 3 < NTILES) fill_w(kt + 3, sw);
            asm volatile("cp.async.commit_group;");
        }

        // stats + roundback tile kt+1
        if (kt + 1 < NTILES) {
            int sn = st5 + 1; if (sn >= 5) sn -= 5;
            stats_round(sn);
        }

        // MMA tile kt
        {
            const float* xs = smem + X_OFF + st5 * XW;
            const float* ws = smem + W_OFF + st4 * WW;
            #pragma unroll
            for (int ks = 0; ks < 4; ks++) {
                uint32_t a[2][4];
                const int kc = ks * 8 + tig;
                #pragma unroll
                for (int s = 0; s < 2; s++) {
                    int mrow = warp_m * 32 + s * 16 + grp;
                    a[s][0] = __float_as_uint(xs[mrow * XROWW + kc]);
                    a[s][1] = __float_as_uint(xs[(mrow + 8) * XROWW + kc]);
                    a[s][2] = __float_as_uint(xs[mrow * XROWW + kc + 4]);
                    a[s][3] = __float_as_uint(xs[(mrow + 8) * XROWW + kc + 4]);
                }
                const int pc = (ks * 4 + tig) * 2;
                #pragma unroll
                for (int j = 0; j < NFRAG; j++) {
                    int nb = (nf0 + j) * 8 + grp;
                    float2 bv = *reinterpret_cast<const float2*>(ws + nb * WROWW + pc);
                    uint32_t b[2] = { __float_as_uint(bv.x), __float_as_uint(bv.y) };
                    mma_tf32(acc[0][j], a[0], b);
                    mma_tf32(acc[1][j], a[1], b);
                }
            }
        }

        if (++st5 == 5) st5 = 0;
        if (++st4 == 4) st4 = 0;
    }

    // Finalize stats: pair (tid, tid^1) holds the two k-halves of row tid>>1
    float stot  = ss  + __shfl_xor_sync(0xffffffffu, ss,  1);
    float stot2 = ss2 + __shfl_xor_sync(0xffffffffu, ss2, 1);
    if ((tid & 1) == 0) {
        int r = tid >> 1;
        float m   = stot * (1.0f / D_DIM);
        float var = fmaxf(stot2 * (1.0f / D_DIM) - m * m, 0.0f);
        smem[MEAN_OFF + r] = m;
        smem[RSTD_OFF + r] = rsqrtf(var + 1e-6f);
    }
    __syncthreads();

    // Epilogue: out = rs*acc + (-rs*mu*S' + cb)
    #pragma unroll
    for (int s = 0; s < 2; s++) {
        const int mrow = warp_m * 32 + s * 16 + grp;
        const float rs0 = smem[RSTD_OFF + mrow];
        const float rs1 = smem[RSTD_OFF + mrow + 8];
        const float nmu0 = -smem[MEAN_OFF + mrow] * rs0;
        const float nmu1 = -smem[MEAN_OFF + mrow + 8] * rs1;
        #pragma unroll
        for (int j = 0; j < NFRAG; j++) {
            int n = (nf0 + j) * 8 + 2 * tig;
            if (n < OUT_DIM) {
                float sp0 = smem[SP_OFF + n],  sp1 = smem[SP_OFF + n + 1];
                float cb0 = smem[CB_OFF + n],  cb1 = smem[CB_OFF + n + 1];
                long long row0 = R0 + mrow;
                float2 v0 = make_float2(fmaf(rs0, acc[s][j][0], fmaf(nmu0, sp0, cb0)),
                                        fmaf(rs0, acc[s][j][1], fmaf(nmu0, sp1, cb1)));
                float2 v1 = make_float2(fmaf(rs1, acc[s][j][2], fmaf(nmu1, sp0, cb0)),
                                        fmaf(rs1, acc[s][j][3], fmaf(nmu1, sp1, cb1)));
                *reinterpret_cast<float2*>(out + row0 * OUT_DIM + n)       = v0;
                *reinterpret_cast<float2*>(out + (row0 + 8) * OUT_DIM + n) = v1;
            }
        }
    }
}

extern "C" void kernel_launch(void* const* d_in, const int* in_sizes, int n_in,
                              void* d_out, int out_size) {
    const float* x     = (const float*)d_in[0];
    const float* gamma = (const float*)d_in[1];
    const float* beta  = (const float*)d_in[2];
    const float* W     = (const float*)d_in[3];
    const float* b     = (const float*)d_in[4];
    float* out = (float*)d_out;

    cudaFuncSetAttribute(ln_gemm_kernel,
                         cudaFuncAttributeMaxDynamicSharedMemorySize, SMEM_BYTES);

    const int rows = in_sizes[0] / D_DIM;   // 65536
    prep_kernel<<<NPAD, D_DIM>>>(W, gamma, beta, b);
    ln_gemm_kernel<<<rows / TM, 256, SMEM_BYTES>>>(x, out);
}